// round 13
// baseline (speedup 1.0000x reference)
#include <cuda_runtime.h>
#include <cuda_fp8.h>
#include <cstdint>
#include <cstddef>

#define N_TOK 8192
#define H_DIM 1024
#define V_DIM 32000

constexpr int BM = 128;
constexpr int BN = 128;
constexpr int BK = 128;            // fp8 K elems per chunk = 128 bytes/row
constexpr int KT = H_DIM / BK;     // 8
constexpr int STAGES = 3;
constexpr int SUB_BYTES = 128 * 64;            // 8192 (sub-block = k64 elems)
constexpr int A_BYTES = 2 * SUB_BYTES;         // 16384
constexpr int B_BYTES = 2 * SUB_BYTES;         // 16384
constexpr int STAGE_BYTES = A_BYTES + B_BYTES; // 32768
constexpr int SMEM_BIAS = STAGES * STAGE_BYTES;  // 98304
constexpr int SMEM_SW   = SMEM_BIAS + 512;
constexpr int SMEM_SX   = SMEM_SW + 512;
constexpr int SMEM_TGT  = SMEM_SX + 512;
constexpr int SMEM_ROW  = SMEM_TGT + 512;
constexpr int SMEM_MBAR = SMEM_ROW + 512;        // full[3] then used[3]
constexpr int SMEM_TOTAL = SMEM_MBAR + 64;       // ~100.9 KB (x2 CTAs)

// Scratch (no cudaMalloc). Referenced ONLY from device code.
__device__ uint8_t g_xq[(size_t)N_TOK * H_DIM];   // 8 MB e4m3
__device__ uint8_t g_wq[(size_t)V_DIM * H_DIM];   // 32 MB e4m3
__device__ float g_sx[N_TOK];
__device__ float g_sw[V_DIM];
__device__ float g_S[N_TOK];
__device__ float g_T[N_TOK];
__device__ int   g_tgt[N_TOK];

// ---------------------------------------------------------------------------
__device__ __forceinline__ uint32_t smem_u32(const void* p) {
    uint32_t a;
    asm("{ .reg .u64 t; cvta.to.shared.u64 t, %1; cvt.u32.u64 %0, t; }" : "=r"(a) : "l"(p));
    return a;
}
__device__ __forceinline__ void cp16(uint32_t daddr, const void* src) {
    asm volatile("cp.async.cg.shared.global [%0], [%1], 16;" :: "r"(daddr), "l"(src));
}
__device__ __forceinline__ void ldsm4(uint32_t* f, uint32_t addr) {
    asm volatile("ldmatrix.sync.aligned.m8n8.x4.shared.b16 {%0,%1,%2,%3}, [%4];"
                 : "=r"(f[0]), "=r"(f[1]), "=r"(f[2]), "=r"(f[3]) : "r"(addr));
}
__device__ __forceinline__ void qmma(float* c, const uint32_t* a, uint32_t b0, uint32_t b1) {
    asm volatile("mma.sync.aligned.m16n8k32.row.col.f32.e4m3.e4m3.f32 "
                 "{%0,%1,%2,%3},{%4,%5,%6,%7},{%8,%9},{%0,%1,%2,%3};"
                 : "+f"(c[0]), "+f"(c[1]), "+f"(c[2]), "+f"(c[3])
                 : "r"(a[0]), "r"(a[1]), "r"(a[2]), "r"(a[3]), "r"(b0), "r"(b1));
}
#define MBAR_INIT(a, n) \
    asm volatile("mbarrier.init.shared.b64 [%0], %1;" :: "r"(a), "r"(n) : "memory")
#define MBAR_WAIT(a, ph) do {                                                   \
    asm volatile("{ .reg .pred P; L%=: mbarrier.try_wait.parity.shared.b64 P, [%0], %1, 0x989680; @P bra D%=; bra L%=; D%=: }" \
        :: "r"(a), "r"(ph) : "memory");                                         \
} while (0)
__device__ __forceinline__ void mbar_arrive(uint32_t a) {
    uint64_t st;
    asm volatile("mbarrier.arrive.shared.b64 %0, [%1];" : "=l"(st) : "r"(a) : "memory");
}
__device__ __forceinline__ void cpasync_mbar_arrive(uint32_t a) {
    asm volatile("cp.async.mbarrier.arrive.noinc.shared.b64 [%0];" :: "r"(a) : "memory");
}

// ---------------------------------------------------------------------------
// Per-row symmetric e4m3 quantization. One warp per row (1024 floats).
// ---------------------------------------------------------------------------
template <int IS_X>
__global__ void quant_rows(const float4* __restrict__ src) {
    const int row  = blockIdx.x * 8 + (threadIdx.x >> 5);
    const int lane = threadIdx.x & 31;
    const float4* s = src + (size_t)row * 256;
    float4 v[8];
    float m = 0.0f;
#pragma unroll
    for (int p = 0; p < 8; p++) {
        v[p] = s[lane + p * 32];
        m = fmaxf(m, fmaxf(fmaxf(fabsf(v[p].x), fabsf(v[p].y)),
                           fmaxf(fabsf(v[p].z), fabsf(v[p].w))));
    }
#pragma unroll
    for (int o = 16; o > 0; o >>= 1) m = fmaxf(m, __shfl_xor_sync(0xffffffffu, m, o));
    m = fmaxf(m, 1e-20f);
    const float inv = 448.0f / m;
    uint32_t* d = (IS_X ? (uint32_t*)g_xq : (uint32_t*)g_wq) + (size_t)row * 256;
#pragma unroll
    for (int p = 0; p < 8; p++) {
        uint32_t b0 = __nv_cvt_float_to_fp8(v[p].x * inv, __NV_SATFINITE, __NV_E4M3);
        uint32_t b1 = __nv_cvt_float_to_fp8(v[p].y * inv, __NV_SATFINITE, __NV_E4M3);
        uint32_t b2 = __nv_cvt_float_to_fp8(v[p].z * inv, __NV_SATFINITE, __NV_E4M3);
        uint32_t b3 = __nv_cvt_float_to_fp8(v[p].w * inv, __NV_SATFINITE, __NV_E4M3);
        d[lane + p * 32] = b0 | (b1 << 8) | (b2 << 16) | (b3 << 24);
    }
    if (lane == 0) {
        if (IS_X) { g_sx[row] = m * (1.0f / 448.0f); g_S[row] = 0.0f; }
        else      { g_sw[row] = m * (1.0f / 448.0f); }
    }
}

// Target dtype sniff (int64 vs int32), normalize to int32.
__global__ void prep_targets_kernel(const int* __restrict__ t) {
    __shared__ int nz;
    if (threadIdx.x == 0) nz = 0;
    __syncthreads();
    int local = 0;
    for (int i = threadIdx.x; i < 4096; i += 256) local |= t[2 * i + 1];
    if (local) atomicOr(&nz, 1);
    __syncthreads();
    bool is64 = (nz == 0);
    for (int i = threadIdx.x; i < N_TOK; i += 256)
        g_tgt[i] = is64 ? t[2 * i] : t[i];
}

// ---------------------------------------------------------------------------
__global__ void __launch_bounds__(256, 2)
gemm_lce_fp8(const float* __restrict__ bias) {
    extern __shared__ char smem[];
    const uint32_t sbase = smem_u32(smem);
    float* sBias = (float*)(smem + SMEM_BIAS);
    float* sSw   = (float*)(smem + SMEM_SW);
    float* sSx   = (float*)(smem + SMEM_SX);
    int*   sTgt  = (int*)  (smem + SMEM_TGT);
    float* sRow  = (float*)(smem + SMEM_ROW);
    const uint32_t mbFull = sbase + SMEM_MBAR;
    const uint32_t mbUsed = mbFull + 24;

    const int tid  = threadIdx.x;
    const int lane = tid & 31;
    const int warp = tid >> 5;
    const int wm   = warp >> 2;
    const int wn   = warp & 3;
    const int g    = lane >> 2;
    const int tig  = lane & 3;

    const int mBase = blockIdx.y * BM;
    const int vBase = blockIdx.x * BN;

    // -------- hoisted loader addressing (proven 64B-row swizzle) -----------
    const char* gA[4]; const char* gB[4];
    uint32_t sA[4], sB[4];
#pragma unroll
    for (int p = 0; p < 4; p++) {
        int idx = tid + p * 256;
        int sub = idx >> 9, rem = idx & 511;
        int row = rem >> 2, cc = rem & 3;
        gA[p] = (const char*)g_xq + (size_t)(mBase + row) * H_DIM + sub * 64 + cc * 16;
        gB[p] = (const char*)g_wq + (size_t)(vBase + row) * H_DIM + sub * 64 + cc * 16;
        uint32_t so = row * 64 + ((cc ^ ((row >> 1) & 3)) << 4) + sub * SUB_BYTES;
        sA[p] = sbase + so;
        sB[p] = sbase + A_BYTES + so;
    }

    // Proven ldmatrix per-lane addressing
    const int rowoff = (lane & 7) + (((lane >> 3) & 1) << 3);
    const int khalf  = lane >> 4;
    const int X      = (rowoff >> 1) & 3;
    const uint32_t offk[2] = { (uint32_t)((khalf ^ X) << 4),
                               (uint32_t)(((2 + khalf) ^ X) << 4) };
    const uint32_t aLane = (uint32_t)((wm * 64 + rowoff) * 64);
    const uint32_t bLane = (uint32_t)(A_BYTES + (wn * 32 + rowoff) * 64);

    if (tid < 128) {
        sRow[tid]  = 0.0f;
        sTgt[tid]  = g_tgt[mBase + tid];
        sBias[tid] = bias[vBase + tid];
        sSw[tid]   = g_sw[vBase + tid];
        sSx[tid]   = g_sx[mBase + tid];
    }
    if (tid == 0) {
#pragma unroll
        for (int s = 0; s < 3; s++) {
            MBAR_INIT(mbFull + s * 8, 256);
            MBAR_INIT(mbUsed + s * 8, 8);
        }
    }
    __syncthreads();

    // Prologue: chunks 0,1 -> slots 0,1
#pragma unroll
    for (int s = 0; s < STAGES - 1; s++) {
        const uint32_t so = (uint32_t)s * STAGE_BYTES;
        const uint32_t ko = (uint32_t)s * 128;
#pragma unroll
        for (int p = 0; p < 4; p++) cp16(sA[p] + so, gA[p] + ko);
#pragma unroll
        for (int p = 0; p < 4; p++) cp16(sB[p] + so, gB[p] + ko);
        cpasync_mbar_arrive(mbFull + s * 8);
    }

    float acc[4][4][4];
#pragma unroll
    for (int i = 0; i < 4; i++)
#pragma unroll
        for (int j = 0; j < 4; j++)
#pragma unroll
            for (int c = 0; c < 4; c++) acc[i][j][c] = 0.0f;

    uint32_t af[2][4][4], bf[2][2][4];

    int c = 0, w = 2;
    uint32_t phF = 0, phU = 0;
    uint32_t kOff = 256;               // byte offset of chunk kt+2

    // Initial: wait chunk 0 data, load its step-0 fragments into buf 0.
    MBAR_WAIT(mbFull, 0u);
    phF ^= 1u;
    {
        const uint32_t aA = sbase + aLane, bA = sbase + bLane;
#pragma unroll
        for (int i = 0; i < 4; i++) ldsm4(af[0][i], aA + i * 1024 + offk[0]);
#pragma unroll
        for (int n = 0; n < 2; n++) ldsm4(bf[0][n], bA + n * 1024 + offk[0]);
    }

    for (int kt = 0; kt < KT; kt++) {
        const uint32_t stg = sbase + (uint32_t)c * STAGE_BYTES;

        // ---- steps 0..2: QMMA + in-chunk fragment prefetch ----
#pragma unroll
        for (int step = 0; step < 3; step++) {
            const int buf = step & 1;
            const int ns = (step + 1) >> 1, nk = (step + 1) & 1;
            const uint32_t aA = stg + ns * SUB_BYTES + aLane;
            const uint32_t bA = stg + ns * SUB_BYTES + bLane;
#pragma unroll
            for (int i = 0; i < 4; i++) ldsm4(af[buf ^ 1][i], aA + i * 1024 + offk[nk]);
#pragma unroll
            for (int n = 0; n < 2; n++) ldsm4(bf[buf ^ 1][n], bA + n * 1024 + offk[nk]);
#pragma unroll
            for (int j = 0; j < 4; j++) {
                const uint32_t b0 = bf[buf][j >> 1][j & 1];
                const uint32_t b1 = bf[buf][j >> 1][2 + (j & 1)];
#pragma unroll
                for (int i = 0; i < 4; i++) qmma(acc[i][j], af[buf][i], b0, b1);
            }
        }

        // ---- producer (mid-chunk: warp already retired 3/4 of its QMMAs) ----
        if (kt + 2 < KT) {
            if (kt >= 1) {
                MBAR_WAIT(mbUsed + w * 8, (phU >> w) & 1);
                phU ^= 1u << w;
            }
            const uint32_t wOff = (uint32_t)w * STAGE_BYTES;
#pragma unroll
            for (int p = 0; p < 4; p++) cp16(sA[p] + wOff, gA[p] + kOff);
#pragma unroll
            for (int p = 0; p < 4; p++) cp16(sB[p] + wOff, gB[p] + kOff);
            cpasync_mbar_arrive(mbFull + w * 8);
            kOff += 128;
        }

        // ---- cross-chunk prefetch: next chunk's step-0 frags into buf 0 ----
        if (kt + 1 < KT) {
            const int cn = (c == 2) ? 0 : c + 1;
            MBAR_WAIT(mbFull + cn * 8, (phF >> cn) & 1);
            phF ^= 1u << cn;
            const uint32_t stgN = sbase + (uint32_t)cn * STAGE_BYTES;
            const uint32_t aA = stgN + aLane, bA = stgN + bLane;
#pragma unroll
            for (int i = 0; i < 4; i++) ldsm4(af[0][i], aA + i * 1024 + offk[0]);
#pragma unroll
            for (int n = 0; n < 2; n++) ldsm4(bf[0][n], bA + n * 1024 + offk[0]);
        }

        // ---- step 3 QMMAs (buf 1), hide the prefetch above ----
#pragma unroll
        for (int j = 0; j < 4; j++) {
            const uint32_t b0 = bf[1][j >> 1][j & 1];
            const uint32_t b1 = bf[1][j >> 1][2 + (j & 1)];
#pragma unroll
            for (int i = 0; i < 4; i++) qmma(acc[i][j], af[1][i], b0, b1);
        }
        if (lane == 0) mbar_arrive(mbUsed + c * 8);

        c = (c == 2) ? 0 : c + 1;
        w = (w == 2) ? 0 : w + 1;
    }
    __syncthreads();

    // -------- Epilogue: scales, bias, exp, row-sums, target ----------------
#pragma unroll
    for (int i = 0; i < 4; i++) {
#pragma unroll
        for (int h = 0; h < 2; h++) {
            const int lr  = wm * 64 + i * 16 + h * 8 + g;
            const int tgt = sTgt[lr];
            const float sx = sSx[lr];
            float s = 0.0f;
#pragma unroll
            for (int j = 0; j < 4; j++) {
                const int cl = wn * 32 + j * 8 + tig * 2;
                float v0 = acc[i][j][h * 2 + 0] * (sx * sSw[cl])     + sBias[cl];
                float v1 = acc[i][j][h * 2 + 1] * (sx * sSw[cl + 1]) + sBias[cl + 1];
                const int gc = vBase + cl;
                if (tgt == gc)     g_T[mBase + lr] = v0;
                if (tgt == gc + 1) g_T[mBase + lr] = v1;
                s += __expf(v0) + __expf(v1);
            }
            s += __shfl_xor_sync(0xffffffffu, s, 1);
            s += __shfl_xor_sync(0xffffffffu, s, 2);
            if (tig == 0) atomicAdd(&sRow[lr], s);
        }
    }
    __syncthreads();
    if (tid < 128) atomicAdd(&g_S[mBase + tid], sRow[tid]);
}

// ---------------------------------------------------------------------------
__global__ void finalize_kernel(float* __restrict__ out) {
    __shared__ double red[256];
    __shared__ int  rcnt[256];
    double a = 0.0;
    int cnt = 0;
    for (int i = threadIdx.x; i < N_TOK; i += 256) {
        if (g_tgt[i] != -100) {
            a += (double)(logf(g_S[i]) - g_T[i]);
            cnt++;
        }
    }
    red[threadIdx.x] = a;
    rcnt[threadIdx.x] = cnt;
    __syncthreads();
    for (int s = 128; s > 0; s >>= 1) {
        if (threadIdx.x < s) {
            red[threadIdx.x]  += red[threadIdx.x + s];
            rcnt[threadIdx.x] += rcnt[threadIdx.x + s];
        }
        __syncthreads();
    }
    if (threadIdx.x == 0) {
        int c = rcnt[0] > 0 ? rcnt[0] : 1;
        out[0] = (float)(red[0] / (double)c);
    }
}

// ---------------------------------------------------------------------------
extern "C" void kernel_launch(void* const* d_in, const int* in_sizes, int n_in,
                              void* d_out, int out_size) {
    const float* x    = (const float*)d_in[0];
    const float* w    = (const float*)d_in[1];
    const float* bias = (const float*)d_in[2];
    const int*   tgt  = (const int*)d_in[3];
    float* out = (float*)d_out;

    cudaFuncSetAttribute(gemm_lce_fp8,
                         cudaFuncAttributeMaxDynamicSharedMemorySize, SMEM_TOTAL);

    quant_rows<1><<<N_TOK / 8, 256>>>((const float4*)x);
    quant_rows<0><<<V_DIM / 8, 256>>>((const float4*)w);
    prep_targets_kernel<<<1, 256>>>(tgt);

    dim3 grid(V_DIM / BN, N_TOK / BM);   // (250, 64) = 16000 CTAs
    gemm_lce_fp8<<<grid, 256, SMEM_TOTAL>>>(bias);

    finalize_kernel<<<1, 256>>>(out);
}

// round 14
// speedup vs baseline: 1.2086x; 1.2086x over previous
#include <cuda_runtime.h>
#include <cuda_fp8.h>
#include <cstdint>
#include <cstddef>

#define N_TOK 8192
#define H_DIM 1024
#define V_DIM 32000

constexpr int BM = 128;
constexpr int BN = 128;
constexpr int BK = 128;            // fp8 K elems per chunk = 128 bytes/row
constexpr int KT = H_DIM / BK;     // 8
constexpr int STAGES = 3;
constexpr int SUB_BYTES = 128 * 64;            // 8192 (sub-block = k64 elems)
constexpr int A_BYTES = 2 * SUB_BYTES;         // 16384
constexpr int B_BYTES = 2 * SUB_BYTES;         // 16384
constexpr int STAGE_BYTES = A_BYTES + B_BYTES; // 32768
constexpr int SMEM_BIAS = STAGES * STAGE_BYTES;  // 98304
constexpr int SMEM_SW   = SMEM_BIAS + 512;
constexpr int SMEM_SX   = SMEM_SW + 512;
constexpr int SMEM_TGT  = SMEM_SX + 512;
constexpr int SMEM_ROW  = SMEM_TGT + 512;
constexpr int SMEM_MBAR = SMEM_ROW + 512;        // full[3] then used[3]
constexpr int SMEM_TOTAL = SMEM_MBAR + 64;       // ~100.9 KB (x2 CTAs)

// Scratch (no cudaMalloc). Referenced ONLY from device code.
__device__ uint8_t g_xq[(size_t)N_TOK * H_DIM];   // 8 MB e4m3
__device__ uint8_t g_wq[(size_t)V_DIM * H_DIM];   // 32 MB e4m3
__device__ float g_sx[N_TOK];
__device__ float g_sw[V_DIM];
__device__ float g_S[N_TOK];
__device__ float g_T[N_TOK];
__device__ int   g_tgt[N_TOK];

// ---------------------------------------------------------------------------
__device__ __forceinline__ uint32_t smem_u32(const void* p) {
    uint32_t a;
    asm("{ .reg .u64 t; cvta.to.shared.u64 t, %1; cvt.u32.u64 %0, t; }" : "=r"(a) : "l"(p));
    return a;
}
__device__ __forceinline__ void cp16(uint32_t daddr, const void* src) {
    asm volatile("cp.async.cg.shared.global [%0], [%1], 16;" :: "r"(daddr), "l"(src));
}
__device__ __forceinline__ void ldsm4(uint32_t* f, uint32_t addr) {
    asm volatile("ldmatrix.sync.aligned.m8n8.x4.shared.b16 {%0,%1,%2,%3}, [%4];"
                 : "=r"(f[0]), "=r"(f[1]), "=r"(f[2]), "=r"(f[3]) : "r"(addr));
}
__device__ __forceinline__ void qmma(float* c, const uint32_t* a, uint32_t b0, uint32_t b1) {
    asm volatile("mma.sync.aligned.m16n8k32.row.col.f32.e4m3.e4m3.f32 "
                 "{%0,%1,%2,%3},{%4,%5,%6,%7},{%8,%9},{%0,%1,%2,%3};"
                 : "+f"(c[0]), "+f"(c[1]), "+f"(c[2]), "+f"(c[3])
                 : "r"(a[0]), "r"(a[1]), "r"(a[2]), "r"(a[3]), "r"(b0), "r"(b1));
}
#define MBAR_INIT(a, n) \
    asm volatile("mbarrier.init.shared.b64 [%0], %1;" :: "r"(a), "r"(n) : "memory")
#define MBAR_WAIT(a, ph) do {                                                   \
    asm volatile("{ .reg .pred P; L%=: mbarrier.try_wait.parity.shared.b64 P, [%0], %1, 0x989680; @P bra D%=; bra L%=; D%=: }" \
        :: "r"(a), "r"(ph) : "memory");                                         \
} while (0)
__device__ __forceinline__ void mbar_arrive(uint32_t a) {
    uint64_t st;
    asm volatile("mbarrier.arrive.shared.b64 %0, [%1];" : "=l"(st) : "r"(a) : "memory");
}
__device__ __forceinline__ void cpasync_mbar_arrive(uint32_t a) {
    asm volatile("cp.async.mbarrier.arrive.noinc.shared.b64 [%0];" :: "r"(a) : "memory");
}

// ---------------------------------------------------------------------------
// Per-row symmetric e4m3 quantization. One warp per row (1024 floats).
// ---------------------------------------------------------------------------
template <int IS_X>
__global__ void quant_rows(const float4* __restrict__ src) {
    const int row  = blockIdx.x * 8 + (threadIdx.x >> 5);
    const int lane = threadIdx.x & 31;
    const float4* s = src + (size_t)row * 256;
    float4 v[8];
    float m = 0.0f;
#pragma unroll
    for (int p = 0; p < 8; p++) {
        v[p] = s[lane + p * 32];
        m = fmaxf(m, fmaxf(fmaxf(fabsf(v[p].x), fabsf(v[p].y)),
                           fmaxf(fabsf(v[p].z), fabsf(v[p].w))));
    }
#pragma unroll
    for (int o = 16; o > 0; o >>= 1) m = fmaxf(m, __shfl_xor_sync(0xffffffffu, m, o));
    m = fmaxf(m, 1e-20f);
    const float inv = 448.0f / m;
    uint32_t* d = (IS_X ? (uint32_t*)g_xq : (uint32_t*)g_wq) + (size_t)row * 256;
#pragma unroll
    for (int p = 0; p < 8; p++) {
        uint32_t b0 = __nv_cvt_float_to_fp8(v[p].x * inv, __NV_SATFINITE, __NV_E4M3);
        uint32_t b1 = __nv_cvt_float_to_fp8(v[p].y * inv, __NV_SATFINITE, __NV_E4M3);
        uint32_t b2 = __nv_cvt_float_to_fp8(v[p].z * inv, __NV_SATFINITE, __NV_E4M3);
        uint32_t b3 = __nv_cvt_float_to_fp8(v[p].w * inv, __NV_SATFINITE, __NV_E4M3);
        d[lane + p * 32] = b0 | (b1 << 8) | (b2 << 16) | (b3 << 24);
    }
    if (lane == 0) {
        if (IS_X) { g_sx[row] = m * (1.0f / 448.0f); g_S[row] = 0.0f; }
        else      { g_sw[row] = m * (1.0f / 448.0f); }
    }
}

// Target dtype sniff (int64 vs int32), normalize to int32.
__global__ void prep_targets_kernel(const int* __restrict__ t) {
    __shared__ int nz;
    if (threadIdx.x == 0) nz = 0;
    __syncthreads();
    int local = 0;
    for (int i = threadIdx.x; i < 4096; i += 256) local |= t[2 * i + 1];
    if (local) atomicOr(&nz, 1);
    __syncthreads();
    bool is64 = (nz == 0);
    for (int i = threadIdx.x; i < N_TOK; i += 256)
        g_tgt[i] = is64 ? t[2 * i] : t[i];
}

// ---------------------------------------------------------------------------
__global__ void __launch_bounds__(256, 2)
gemm_lce_fp8(const float* __restrict__ bias) {
    extern __shared__ char smem[];
    const uint32_t sbase = smem_u32(smem);
    float* sBias = (float*)(smem + SMEM_BIAS);
    float* sSw   = (float*)(smem + SMEM_SW);
    float* sSx   = (float*)(smem + SMEM_SX);
    int*   sTgt  = (int*)  (smem + SMEM_TGT);
    float* sRow  = (float*)(smem + SMEM_ROW);
    const uint32_t mbFull = sbase + SMEM_MBAR;
    const uint32_t mbUsed = mbFull + 24;

    const int tid  = threadIdx.x;
    const int lane = tid & 31;
    const int warp = tid >> 5;
    const int wm   = warp >> 2;
    const int wn   = warp & 3;
    const int g    = lane >> 2;
    const int tig  = lane & 3;

    const int mBase = blockIdx.y * BM;
    const int vBase = blockIdx.x * BN;

    // -------- hoisted loader addressing (proven 64B-row swizzle) -----------
    const char* gA[4]; const char* gB[4];
    uint32_t sA[4], sB[4];
#pragma unroll
    for (int p = 0; p < 4; p++) {
        int idx = tid + p * 256;
        int sub = idx >> 9, rem = idx & 511;
        int row = rem >> 2, cc = rem & 3;
        gA[p] = (const char*)g_xq + (size_t)(mBase + row) * H_DIM + sub * 64 + cc * 16;
        gB[p] = (const char*)g_wq + (size_t)(vBase + row) * H_DIM + sub * 64 + cc * 16;
        uint32_t so = row * 64 + ((cc ^ ((row >> 1) & 3)) << 4) + sub * SUB_BYTES;
        sA[p] = sbase + so;
        sB[p] = sbase + A_BYTES + so;
    }

    // Proven ldmatrix per-lane addressing
    const int rowoff = (lane & 7) + (((lane >> 3) & 1) << 3);
    const int khalf  = lane >> 4;
    const int X      = (rowoff >> 1) & 3;
    const uint32_t offk[2] = { (uint32_t)((khalf ^ X) << 4),
                               (uint32_t)(((2 + khalf) ^ X) << 4) };
    const uint32_t aLane = (uint32_t)((wm * 64 + rowoff) * 64);
    const uint32_t bLane = (uint32_t)(A_BYTES + (wn * 32 + rowoff) * 64);

    if (tid < 128) {
        sRow[tid]  = 0.0f;
        sTgt[tid]  = g_tgt[mBase + tid];
        sBias[tid] = bias[vBase + tid];
        sSw[tid]   = g_sw[vBase + tid];
        sSx[tid]   = g_sx[mBase + tid];
    }
    if (tid == 0) {
#pragma unroll
        for (int s = 0; s < 3; s++) {
            MBAR_INIT(mbFull + s * 8, 256);
            MBAR_INIT(mbUsed + s * 8, 8);
        }
    }
    __syncthreads();

    // Prologue: chunks 0,1 -> slots 0,1
#pragma unroll
    for (int s = 0; s < STAGES - 1; s++) {
        const uint32_t so = (uint32_t)s * STAGE_BYTES;
        const uint32_t ko = (uint32_t)s * 128;
#pragma unroll
        for (int p = 0; p < 4; p++) cp16(sA[p] + so, gA[p] + ko);
#pragma unroll
        for (int p = 0; p < 4; p++) cp16(sB[p] + so, gB[p] + ko);
        cpasync_mbar_arrive(mbFull + s * 8);
    }

    float acc[4][4][4];
#pragma unroll
    for (int i = 0; i < 4; i++)
#pragma unroll
        for (int j = 0; j < 4; j++)
#pragma unroll
            for (int c = 0; c < 4; c++) acc[i][j][c] = 0.0f;

    uint32_t af[2][4][4], bf[2][2][4];

    int c = 0, w = 2;
    uint32_t phF = 0, phU = 0;
    uint32_t kOff = 256;               // byte offset of chunk kt+2

    for (int kt = 0; kt < KT; kt++) {
        // ---- consumer: wait data, compute full chunk first ----
        MBAR_WAIT(mbFull + c * 8, (phF >> c) & 1);
        phF ^= 1u << c;

        const uint32_t stg = sbase + (uint32_t)c * STAGE_BYTES;
        {
            const uint32_t aA = stg + aLane, bA = stg + bLane;
#pragma unroll
            for (int i = 0; i < 4; i++) ldsm4(af[0][i], aA + i * 1024 + offk[0]);
#pragma unroll
            for (int n = 0; n < 2; n++) ldsm4(bf[0][n], bA + n * 1024 + offk[0]);
        }
#pragma unroll
        for (int step = 0; step < 4; step++) {      // (sub,k32half) micro-steps
            const int buf = step & 1;
            if (step < 3) {
                const int ns = (step + 1) >> 1, nk = (step + 1) & 1;
                const uint32_t aA = stg + ns * SUB_BYTES + aLane;
                const uint32_t bA = stg + ns * SUB_BYTES + bLane;
#pragma unroll
                for (int i = 0; i < 4; i++) ldsm4(af[buf ^ 1][i], aA + i * 1024 + offk[nk]);
#pragma unroll
                for (int n = 0; n < 2; n++) ldsm4(bf[buf ^ 1][n], bA + n * 1024 + offk[nk]);
            }
#pragma unroll
            for (int j = 0; j < 4; j++) {
                const uint32_t b0 = bf[buf][j >> 1][j & 1];
                const uint32_t b1 = bf[buf][j >> 1][2 + (j & 1)];
#pragma unroll
                for (int i = 0; i < 4; i++) qmma(acc[i][j], af[buf][i], b0, b1);
            }
        }
        if (lane == 0) mbar_arrive(mbUsed + c * 8);

        // ---- producer at END: warp retired its chunk before it can block ----
        if (kt + 2 < KT) {
            if (kt >= 1) {             // slot w held chunk kt-1; wait its consumption
                MBAR_WAIT(mbUsed + w * 8, (phU >> w) & 1);
                phU ^= 1u << w;
            }
            const uint32_t wOff = (uint32_t)w * STAGE_BYTES;
#pragma unroll
            for (int p = 0; p < 4; p++) cp16(sA[p] + wOff, gA[p] + kOff);
#pragma unroll
            for (int p = 0; p < 4; p++) cp16(sB[p] + wOff, gB[p] + kOff);
            cpasync_mbar_arrive(mbFull + w * 8);
            kOff += 128;
        }

        c = (c == 2) ? 0 : c + 1;
        w = (w == 2) ? 0 : w + 1;
    }
    __syncthreads();

    // -------- Epilogue: scales, bias, exp, row-sums, target ----------------
#pragma unroll
    for (int i = 0; i < 4; i++) {
#pragma unroll
        for (int h = 0; h < 2; h++) {
            const int lr  = wm * 64 + i * 16 + h * 8 + g;
            const int tgt = sTgt[lr];
            const float sx = sSx[lr];
            float s = 0.0f;
#pragma unroll
            for (int j = 0; j < 4; j++) {
                const int cl = wn * 32 + j * 8 + tig * 2;
                float v0 = acc[i][j][h * 2 + 0] * (sx * sSw[cl])     + sBias[cl];
                float v1 = acc[i][j][h * 2 + 1] * (sx * sSw[cl + 1]) + sBias[cl + 1];
                const int gc = vBase + cl;
                if (tgt == gc)     g_T[mBase + lr] = v0;
                if (tgt == gc + 1) g_T[mBase + lr] = v1;
                s += __expf(v0) + __expf(v1);
            }
            s += __shfl_xor_sync(0xffffffffu, s, 1);
            s += __shfl_xor_sync(0xffffffffu, s, 2);
            if (tig == 0) atomicAdd(&sRow[lr], s);
        }
    }
    __syncthreads();
    if (tid < 128) atomicAdd(&g_S[mBase + tid], sRow[tid]);
}

// ---------------------------------------------------------------------------
__global__ void finalize_kernel(float* __restrict__ out) {
    __shared__ double red[256];
    __shared__ int  rcnt[256];
    double a = 0.0;
    int cnt = 0;
    for (int i = threadIdx.x; i < N_TOK; i += 256) {
        if (g_tgt[i] != -100) {
            a += (double)(logf(g_S[i]) - g_T[i]);
            cnt++;
        }
    }
    red[threadIdx.x] = a;
    rcnt[threadIdx.x] = cnt;
    __syncthreads();
    for (int s = 128; s > 0; s >>= 1) {
        if (threadIdx.x < s) {
            red[threadIdx.x]  += red[threadIdx.x + s];
            rcnt[threadIdx.x] += rcnt[threadIdx.x + s];
        }
        __syncthreads();
    }
    if (threadIdx.x == 0) {
        int c = rcnt[0] > 0 ? rcnt[0] : 1;
        out[0] = (float)(red[0] / (double)c);
    }
}

// ---------------------------------------------------------------------------
extern "C" void kernel_launch(void* const* d_in, const int* in_sizes, int n_in,
                              void* d_out, int out_size) {
    const float* x    = (const float*)d_in[0];
    const float* w    = (const float*)d_in[1];
    const float* bias = (const float*)d_in[2];
    const int*   tgt  = (const int*)d_in[3];
    float* out = (float*)d_out;

    cudaFuncSetAttribute(gemm_lce_fp8,
                         cudaFuncAttributeMaxDynamicSharedMemorySize, SMEM_TOTAL);

    quant_rows<1><<<N_TOK / 8, 256>>>((const float4*)x);
    quant_rows<0><<<V_DIM / 8, 256>>>((const float4*)w);
    prep_targets_kernel<<<1, 256>>>(tgt);

    dim3 grid(V_DIM / BN, N_TOK / BM);   // (250, 64) = 16000 CTAs
    gemm_lce_fp8<<<grid, 256, SMEM_TOTAL>>>(bias);

    finalize_kernel<<<1, 256>>>(out);
}